// round 14
// baseline (speedup 1.0000x reference)
#include <cuda_runtime.h>
#include <cuda_fp16.h>
#include <cstdint>
#include <math.h>

#define H 256
#define W 256
#define B 4
#define HW 65536

// ---------------- scratch (static device globals; no runtime allocation) ----
// Activation scratch: per pixel-pair one uint2 {hi fp16x2, lo fp16x2}
// at uint2 index (b*PAIRS + pair)*HW + pix  (hi/lo interleaved).
__device__ float g_fin [2 * B * 16 * HW];   // fusion_in,  16 pair-planes (12 real)
__device__ float g_bufA[2 * B * 32 * HW];   // conv1/conv4 out (32 pairs)
__device__ float g_bufB[2 * B * 32 * HW];   // conv2/conv5 out
__device__ float g_din [2 * B * 56 * HW];   // denoise_in, 56 pair-planes (50 real)
__device__ float g_wsc [57600 * 2];         // pre-split weights (uint2 units)

// ---------------- PTX helpers ------------------------------------------------
__device__ __forceinline__ uint32_t smem_u32(const void* p) {
    uint32_t a;
    asm("{ .reg .u64 t; cvta.to.shared.u64 t, %1; cvt.u32.u64 %0, t; }"
        : "=r"(a) : "l"(p));
    return a;
}
#define CP_ASYNC8(dst, src) \
    asm volatile("cp.async.ca.shared.global [%0], [%1], 8;" \
        :: "r"(dst), "l"(src))
#define CP_ASYNC16Z(dst, src, sz) \
    asm volatile("cp.async.cg.shared.global [%0], [%1], 16, %2;" \
        :: "r"(dst), "l"(src), "r"(sz))
#define CP_COMMIT() asm volatile("cp.async.commit_group;" ::: "memory")
#define CP_WAIT0()  asm volatile("cp.async.wait_group 0;" ::: "memory")
#define CP_WAIT1()  asm volatile("cp.async.wait_group 1;" ::: "memory")

__device__ __forceinline__ void mma_f16(float* c, const uint32_t* a,
                                        uint32_t b0, uint32_t b1) {
    asm volatile(
        "mma.sync.aligned.m16n8k16.row.col.f32.f16.f16.f32 "
        "{%0,%1,%2,%3}, {%4,%5,%6,%7}, {%8,%9}, {%0,%1,%2,%3};"
        : "+f"(c[0]), "+f"(c[1]), "+f"(c[2]), "+f"(c[3])
        : "r"(a[0]), "r"(a[1]), "r"(a[2]), "r"(a[3]), "r"(b0), "r"(b1));
}
// activation pack: hi = f16x2(v0,v1), lo = f16x2 of residuals
__device__ __forceinline__ uint2 packA2(float v0, float v1) {
    __half2 hh = __floats2half2_rn(v0, v1);
    uint32_t h = *reinterpret_cast<uint32_t*>(&hh);
    float r0 = v0 - __low2float(hh);
    float r1 = v1 - __high2float(hh);
    __half2 ll = __floats2half2_rn(r0, r1);
    uint32_t l = *reinterpret_cast<uint32_t*>(&ll);
    return make_uint2(h, l);
}
__device__ __forceinline__ uint32_t pack1(float v0, float v1) {
    __half2 hh = __floats2half2_rn(v0, v1);
    return *reinterpret_cast<uint32_t*>(&hh);
}

// ================ weight pre-split: ALL 6 convs in one launch ================
// Per chunk (16 cin): [tap][co 0..63][tig 0..3] uint2 = {b(pair tig), b(pair tig+4)}
__global__ void split_all(const float* __restrict__ w1, const float* __restrict__ w2,
                          const float* __restrict__ w3, const float* __restrict__ w4,
                          const float* __restrict__ w5, const float* __restrict__ w6,
                          uint2* __restrict__ dst)
{
    int idx = blockIdx.x * blockDim.x + threadIdx.x;
    if (idx >= 25 * 2304) return;
    int cg = idx / 2304;
    int r  = idx % 2304;
    const float* w; int CIN, COUT, ch;
    if      (cg < 2)  { w = w1; CIN = 24;  COUT = 64; ch = cg; }
    else if (cg < 6)  { w = w2; CIN = 64;  COUT = 64; ch = cg - 2; }
    else if (cg < 10) { w = w3; CIN = 64;  COUT = 4;  ch = cg - 6; }
    else if (cg < 17) { w = w4; CIN = 100; COUT = 64; ch = cg - 10; }
    else if (cg < 21) { w = w5; CIN = 64;  COUT = 64; ch = cg - 17; }
    else              { w = w6; CIN = 64;  COUT = 64; ch = cg - 21; }
    int tap = r / 256;
    int co  = (r % 256) >> 2;
    int tig = r & 3;
    auto f = [&](int k) -> float {
        return (co < COUT && k < CIN) ? w[((size_t)co * CIN + k) * 9 + tap] : 0.f;
    };
    int k0 = ch * 16 + tig * 2;
    int k1 = ch * 16 + (tig + 4) * 2;
    dst[idx] = make_uint2(pack1(f(k0), f(k0 + 1)), pack1(f(k1), f(k1 + 1)));
}

// ================ fp16 2-term mma.sync implicit-GEMM 3x3 conv ================
// Block 256 thr (8 warps) = 2 rows x 128 px; warp w -> row (w>>2),
// px [(w&3)*32, +32). Chunk = 16 cin (8 pairs); A double-buffered (16B
// cp.async over 4 input rows), W single-buffered.
// A smem (uint2 units): [buf][pair][trow 0..3][142] {hi,lo} interleaved;
//   pair stride 580 u2 (word stride 1160 == 8 mod 32): LDS.64 phases hit
//   bank-pairs {0,4,8,12}+g -> conflict-free. u2 index xl' <-> gx = x0+xl'-4.
// W smem: [tap][co][tig] uint2 (restaged per chunk).
// Per tap: 8 A-LDS.64 + 8 W-LDS.64, then 16 hi-MMAs + 16 lo-MMAs.
template <int PA, int PR, int COUT, int NT8, int ACT, int TO_F32, int FUSE>
__global__ void __launch_bounds__(256, 2)
conv_f16(const uint2* __restrict__ inp, const uint2* __restrict__ wsc,
         const float* __restrict__ bias, float* __restrict__ outf,
         uint2* __restrict__ outs,
         const float* __restrict__ ft0, const float* __restrict__ ft1,
         const float* __restrict__ dd, const float* __restrict__ ca,
         const float* __restrict__ cb, float* __restrict__ out_fusion,
         float* __restrict__ out_sigma, uint2* __restrict__ din)
{
    constexpr int NC    = PA / 8;
    constexpr int RSU   = 142;             // row stride (uint2)
    constexpr int PSTRU = 580;             // pair stride (uint2): 4*142+12, word 1160==8 mod 32
    constexpr int ASTG  = 8 * PSTRU;       // 4640 uint2 per A stage
    constexpr int PO    = (COUT >= 8) ? COUT / 2 : 2;

    extern __shared__ uint2 sm2[];
    uint2* smA2 = sm2;                     // [2][ASTG]
    uint2* smW  = sm2 + 2 * ASTG;          // [2304]
    const uint32_t a_u = smem_u32(smA2);
    const uint32_t w_u = smem_u32(smW);

    const int tid  = threadIdx.x;
    const int wid  = tid >> 5;
    const int lane = tid & 31;
    const int tig  = lane & 3;
    const int g    = lane >> 2;
    const int wr   = wid >> 2;             // warp's row within block (0/1)
    const int wx   = (wid & 3) * 32;       // warp's px base within 128
    const int y0   = (blockIdx.x >> 1) * 2;
    const int x0   = (blockIdx.x & 1) * 128;
    const int b    = blockIdx.y;

    float acc[2][NT8][4];
#pragma unroll
    for (int mi = 0; mi < 2; mi++)
#pragma unroll
        for (int nt = 0; nt < NT8; nt++)
#pragma unroll
            for (int e = 0; e < 4; e++) acc[mi][nt][e] = 0.f;

    // ---- A stager: 16B groups = 2 px of {hi,lo}; 8 pairs x 4 rows x 70 ----
    auto issue_A = [&](int ch, int buf) {
#pragma unroll 1
        for (int i = tid; i < 2240; i += 256) {
            int j    = i % 70;
            int row  = i / 70;             // pr*4 + tr
            int tr   = row & 3;
            int pr   = row >> 2;
            int pair = ch * 8 + pr;
            int gy   = y0 + tr - 1;
            int gx0  = x0 - 4 + 2 * j;
            bool v = (gy >= 0) & (gy < H) & (gx0 >= 0) & (gx0 < W) &
                     (PA == PR || pair < PR);
            size_t so = v ? ((size_t)(b * PA + pair) * HW + (size_t)gy * W + gx0) : 0;
            uint32_t dA = a_u + (uint32_t)(buf * ASTG + pr * PSTRU + tr * RSU + 2 * j) * 8u;
            CP_ASYNC16Z(dA, inp + so, v ? 16 : 0);
        }
    };
    auto issue_W = [&](int ch) {
        const uint2* ws = wsc + ch * 2304;
#pragma unroll 1
        for (int i = tid; i < 2304; i += 256)
            CP_ASYNC8(w_u + (uint32_t)i * 8u, ws + i);
    };

    issue_A(0, 0);
    CP_COMMIT();

    for (int ch = 0; ch < NC; ch++) {
        issue_W(ch);
        CP_COMMIT();
        if (ch + 1 < NC) {
            issue_A(ch + 1, (ch + 1) & 1);
            CP_COMMIT();
            CP_WAIT1();                    // A(ch) + W(ch) complete
        } else {
            CP_WAIT0();
        }
        __syncthreads();

        const uint2* A2 = smA2 + (ch & 1) * ASTG;
        const uint2* Wb = smW;
        const int xb = wx + g + 3;         // u2 index base (px' = px_local + 4)
        const int s0 = tig * PSTRU;
        const int s4 = s0 + 4 * PSTRU;

#pragma unroll
        for (int tap = 0; tap < 9; tap++) {
            const int dy = tap / 3, dx = tap % 3;
            const int rof = (wr + dy) * RSU + xb + dx;
            uint32_t aH[2][4], aL[2][4];
#pragma unroll
            for (int mi = 0; mi < 2; mi++) {
                const int base = rof + mi * 16;
                uint2 t0 = A2[s0 + base];
                uint2 t1 = A2[s0 + base + 8];
                uint2 t2 = A2[s4 + base];
                uint2 t3 = A2[s4 + base + 8];
                aH[mi][0] = t0.x; aL[mi][0] = t0.y;
                aH[mi][1] = t1.x; aL[mi][1] = t1.y;
                aH[mi][2] = t2.x; aL[mi][2] = t2.y;
                aH[mi][3] = t3.x; aL[mi][3] = t3.y;
            }
            uint2 wreg[NT8];
#pragma unroll
            for (int nt = 0; nt < NT8; nt++)
                wreg[nt] = Wb[tap * 256 + (nt * 8 + g) * 4 + tig];
#pragma unroll
            for (int nt = 0; nt < NT8; nt++) {       // hi pass
                mma_f16(acc[0][nt], aH[0], wreg[nt].x, wreg[nt].y);
                mma_f16(acc[1][nt], aH[1], wreg[nt].x, wreg[nt].y);
            }
#pragma unroll
            for (int nt = 0; nt < NT8; nt++) {       // lo pass
                mma_f16(acc[0][nt], aL[0], wreg[nt].x, wreg[nt].y);
                mma_f16(acc[1][nt], aL[1], wreg[nt].x, wreg[nt].y);
            }
        }
        __syncthreads();
    }

    // ---- epilogue ----
    const int yout = y0 + wr;
    float* gsm = (float*)smA2;             // reused (all reads done)
#pragma unroll
    for (int nt = 0; nt < NT8; nt++) {
        const int co0 = nt * 8 + tig * 2;
        if (COUT < 8 && co0 >= COUT) continue;
        const float bs0 = __ldg(&bias[co0]);
        const float bs1 = __ldg(&bias[co0 + 1]);
#pragma unroll
        for (int mi = 0; mi < 2; mi++) {
            const int px = wx + mi * 16 + g;
            float v0 = acc[mi][nt][0] + bs0;
            float v1 = acc[mi][nt][1] + bs1;
            float v2 = acc[mi][nt][2] + bs0;
            float v3 = acc[mi][nt][3] + bs1;
            if (ACT == 0) {
                v0 = fmaxf(v0, 0.f); v1 = fmaxf(v1, 0.f);
                v2 = fmaxf(v2, 0.f); v3 = fmaxf(v3, 0.f);
            } else if (ACT == 1) {
                v0 = 1.f / (1.f + __expf(-v0)); v1 = 1.f / (1.f + __expf(-v1));
                v2 = 1.f / (1.f + __expf(-v2)); v3 = 1.f / (1.f + __expf(-v3));
            }
            if (TO_F32) {
                float* o0 = outf + ((size_t)b * COUT + co0) * HW
                            + (size_t)yout * W + x0;
                float* o1 = o0 + HW;
                o0[px]     = v0;  o1[px]     = v1;
                o0[px + 8] = v2;  o1[px + 8] = v3;
            } else {
                const int pair = nt * 4 + tig;
                size_t o = (size_t)(b * PO + pair) * HW + (size_t)yout * W + x0 + px;
                outs[o]     = packA2(v0, v1);
                outs[o + 8] = packA2(v2, v3);
            }
            if (FUSE) {                    // gamma -> smem [c][row][px]
                gsm[(co0)     * 264 + wr * 132 + px]     = v0;
                gsm[(co0 + 1) * 264 + wr * 132 + px]     = v1;
                gsm[(co0)     * 264 + wr * 132 + px + 8] = v2;
                gsm[(co0 + 1) * 264 + wr * 132 + px + 8] = v3;
            }
        }
    }

    // ---- fused elementwise stage (conv3 only): fusion_out / sigma / din ----
    if (FUSE) {
        __syncthreads();
        const int row = tid >> 7;          // 0/1
        const int px  = tid & 127;
        const int q   = (y0 + row) * W + x0 + px;
        const float* f0 = ft0 + (size_t)b * 64 * HW + q;
        const float* f1 = ft1 + (size_t)b * 64 * HW + q;
        const float* dv = dd  + (size_t)b * 16 * HW + q;
        float* ofu = out_fusion + (size_t)b * 64 * HW + q;
        float* osg = out_sigma  + (size_t)b * 4 * HW + q;
        const float a = *ca, bo = *cb;

        float g4[4];
#pragma unroll
        for (int c = 0; c < 4; c++) g4[c] = gsm[c * 264 + row * 132 + px];

        auto st = [&](int pair, float v0, float v1) {
            din[(size_t)(b * 56 + pair) * HW + q] = packA2(v0, v1);
        };
#pragma unroll
        for (int c = 0; c < 32; c++) {
            float t00 = f0[(size_t)(2 * c) * HW],     t10 = f1[(size_t)(2 * c) * HW];
            float t01 = f0[(size_t)(2 * c + 1) * HW], t11 = f1[(size_t)(2 * c + 1) * HW];
            float gm = g4[c >> 3];
            float r0 = t00 + gm * (t10 - t00);
            float r1 = t01 + gm * (t11 - t01);
            ofu[(size_t)(2 * c) * HW]     = r0;
            ofu[(size_t)(2 * c + 1) * HW] = r1;
            st(c, r0, r1);
        }
#pragma unroll
        for (int j = 0; j < 8; j++)
            st(32 + j, f1[(size_t)(2 * j) * HW], f1[(size_t)(2 * j + 1) * HW]);
#pragma unroll
        for (int j = 0; j < 8; j++)
            st(40 + j, dv[(size_t)(2 * j) * HW], dv[(size_t)(2 * j + 1) * HW]);
        float sg[4];
#pragma unroll
        for (int c = 0; c < 4; c++) {
            float s0 = fminf(fmaxf(f0[(size_t)c * HW], 0.f), 1.f) * a + bo;
            float s1 = fminf(fmaxf(f1[(size_t)c * HW], 0.f), 1.f) * a + bo;
            float om = 1.f - g4[c];
            sg[c] = om * om * s0 + g4[c] * g4[c] * s1;
            osg[(size_t)c * HW] = sg[c];
        }
        st(48, sg[0], sg[1]);
        st(49, sg[2], sg[3]);
    }
}

// ---------------- prep: fusion_in -> interleaved {hi,lo} uint2 ---------------
__global__ void prep_kernel(const float* __restrict__ ft0,
                            const float* __restrict__ ft1,
                            const float* __restrict__ gup,
                            const float* __restrict__ ca,
                            const float* __restrict__ cb,
                            uint2* __restrict__ fin)
{
    int p = blockIdx.x * blockDim.x + threadIdx.x;
    if (p >= B * HW) return;
    int b = p >> 16;
    int q = p & (HW - 1);
    const float* f0 = ft0 + (size_t)b * 64 * HW + q;
    const float* f1 = ft1 + (size_t)b * 64 * HW + q;
    const float* gu = gup + (size_t)b * 4 * HW + q;
    float a = *ca, bo = *cb;

    auto st = [&](int pair, float v0, float v1) {
        fin[(size_t)(b * 16 + pair) * HW + q] = packA2(v0, v1);
    };
#pragma unroll
    for (int i = 0; i < 8; i++) {
        float d0 = fabsf(f1[(size_t)(2 * i) * HW]     - f0[(size_t)(2 * i) * HW]);
        float d1 = fabsf(f1[(size_t)(2 * i + 1) * HW] - f0[(size_t)(2 * i + 1) * HW]);
        st(i, d0, d1);
    }
    st(8, gu[0], gu[(size_t)1 * HW]);
    st(9, gu[(size_t)2 * HW], gu[(size_t)3 * HW]);
#pragma unroll
    for (int i = 0; i < 2; i++) {
        float s0 = fminf(fmaxf(f1[(size_t)(2 * i) * HW],     0.f), 1.f) * a + bo;
        float s1 = fminf(fmaxf(f1[(size_t)(2 * i + 1) * HW], 0.f), 1.f) * a + bo;
        st(10 + i, s0, s1);
    }
}

// ---------------- launch -----------------------------------------------------
template <int PA, int PR, int COUT, int NT8, int ACT, int TO_F32, int FUSE>
static inline void launch_conv(const uint2* in, const uint2* w,
                               const float* bi, float* of, uint2* os,
                               const float* ft0 = nullptr, const float* ft1 = nullptr,
                               const float* dd = nullptr, const float* ca = nullptr,
                               const float* cb = nullptr, float* ofu = nullptr,
                               float* osg = nullptr, uint2* din = nullptr)
{
    constexpr int SMEM = (2 * 4640 + 2304) * 8;   // 92672 B -> 2 CTAs/SM
    cudaFuncSetAttribute(conv_f16<PA, PR, COUT, NT8, ACT, TO_F32, FUSE>,
                         cudaFuncAttributeMaxDynamicSharedMemorySize, SMEM);
    conv_f16<PA, PR, COUT, NT8, ACT, TO_F32, FUSE>
        <<<dim3(H, B), 256, SMEM>>>(in, w, bi, of, os,
                                    ft0, ft1, dd, ca, cb, ofu, osg, din);
}

extern "C" void kernel_launch(void* const* d_in, const int* in_sizes, int n_in,
                              void* d_out, int out_size)
{
    const float* ft0 = (const float*)d_in[0];
    const float* ft1 = (const float*)d_in[1];
    const float* gup = (const float*)d_in[2];
    const float* dd  = (const float*)d_in[3];
    const float* ca  = (const float*)d_in[4];
    const float* cb  = (const float*)d_in[5];
    const float* fw1 = (const float*)d_in[6];
    const float* fb1 = (const float*)d_in[7];
    const float* fw2 = (const float*)d_in[8];
    const float* fb2 = (const float*)d_in[9];
    const float* fw3 = (const float*)d_in[10];
    const float* fb3 = (const float*)d_in[11];
    const float* dw1 = (const float*)d_in[12];
    const float* db1 = (const float*)d_in[13];
    const float* dw2 = (const float*)d_in[14];
    const float* db2 = (const float*)d_in[15];
    const float* dw3 = (const float*)d_in[16];
    const float* db3 = (const float*)d_in[17];

    float* out        = (float*)d_out;
    float* out_fusion = out;
    float* out_den    = out + (size_t)B * 64 * HW;
    float* out_gamma  = out + (size_t)2 * B * 64 * HW;
    float* out_sigma  = out_gamma + (size_t)B * 4 * HW;

    float *fin_f, *bufA_f, *bufB_f, *din_f, *wsc_f;
    cudaGetSymbolAddress((void**)&fin_f,  g_fin);
    cudaGetSymbolAddress((void**)&bufA_f, g_bufA);
    cudaGetSymbolAddress((void**)&bufB_f, g_bufB);
    cudaGetSymbolAddress((void**)&din_f,  g_din);
    cudaGetSymbolAddress((void**)&wsc_f,  g_wsc);
    uint2* fin  = (uint2*)fin_f;
    uint2* bufA = (uint2*)bufA_f;
    uint2* bufB = (uint2*)bufB_f;
    uint2* din  = (uint2*)din_f;
    uint2* wsc  = (uint2*)wsc_f;

    // chunk offsets (x2304 uint2): w1@0(2) w2@2(4) w3@6(4) w4@10(7) w5@17(4) w6@21(4)
    split_all<<<(25 * 2304 + 255) / 256, 256>>>(fw1, fw2, fw3, dw1, dw2, dw3, wsc);

    prep_kernel<<<(B * HW + 255) / 256, 256>>>(ft0, ft1, gup, ca, cb, fin);

    launch_conv<16, 12, 64, 8, 0, 0, 0>(fin,  wsc,              fb1, nullptr, bufA);
    launch_conv<32, 32, 64, 8, 0, 0, 0>(bufA, wsc + 2  * 2304,  fb2, nullptr, bufB);
    launch_conv<32, 32,  4, 1, 1, 1, 1>(bufB, wsc + 6  * 2304,  fb3, out_gamma, nullptr,
                                        ft0, ft1, dd, ca, cb,
                                        out_fusion, out_sigma, din);
    launch_conv<56, 50, 64, 8, 0, 0, 0>(din,  wsc + 10 * 2304,  db1, nullptr, bufA);
    launch_conv<32, 32, 64, 8, 0, 0, 0>(bufA, wsc + 17 * 2304,  db2, nullptr, bufB);
    launch_conv<32, 32, 64, 8, 2, 1, 0>(bufB, wsc + 21 * 2304,  db3, out_den, nullptr);
}

// round 16
// speedup vs baseline: 1.1376x; 1.1376x over previous
#include <cuda_runtime.h>
#include <cuda_fp16.h>
#include <cstdint>
#include <math.h>

#define H 256
#define W 256
#define B 4
#define HW 65536

// ---------------- scratch (static device globals; no runtime allocation) ----
// Activation scratch: fp16x2 pair-packed, [hi | lo] plane halves.
__device__ float g_fin [2 * B * 16 * HW];   // fusion_in,  16 pair-planes (12 real)
__device__ float g_bufA[2 * B * 32 * HW];   // conv1/conv4 out (32 pairs)
__device__ float g_bufB[2 * B * 32 * HW];   // conv2/conv5 out
__device__ float g_din [2 * B * 56 * HW];   // denoise_in, 56 pair-planes (50 real)
__device__ float g_wsc [57600 * 2];         // pre-split weights (uint2 units)

// ---------------- PTX helpers ------------------------------------------------
__device__ __forceinline__ uint32_t smem_u32(const void* p) {
    uint32_t a;
    asm("{ .reg .u64 t; cvta.to.shared.u64 t, %1; cvt.u32.u64 %0, t; }"
        : "=r"(a) : "l"(p));
    return a;
}
#define CP_ASYNC16(dst, src) \
    asm volatile("cp.async.ca.shared.global [%0], [%1], 16;" \
        :: "r"(dst), "l"(src))
#define CP_ASYNC16Z(dst, src, sz) \
    asm volatile("cp.async.cg.shared.global [%0], [%1], 16, %2;" \
        :: "r"(dst), "l"(src), "r"(sz))
#define CP_COMMIT() asm volatile("cp.async.commit_group;" ::: "memory")
#define CP_WAIT0()  asm volatile("cp.async.wait_group 0;" ::: "memory")
#define CP_WAIT1()  asm volatile("cp.async.wait_group 1;" ::: "memory")

__device__ __forceinline__ void mma_f16(float* c, const uint32_t* a,
                                        uint32_t b0, uint32_t b1) {
    asm volatile(
        "mma.sync.aligned.m16n8k16.row.col.f32.f16.f16.f32 "
        "{%0,%1,%2,%3}, {%4,%5,%6,%7}, {%8,%9}, {%0,%1,%2,%3};"
        : "+f"(c[0]), "+f"(c[1]), "+f"(c[2]), "+f"(c[3])
        : "r"(a[0]), "r"(a[1]), "r"(a[2]), "r"(a[3]), "r"(b0), "r"(b1));
}
// activation pack: hi = f16x2(v0,v1), lo = f16x2 of residuals
__device__ __forceinline__ void packA(float v0, float v1,
                                      uint32_t& h, uint32_t& l) {
    __half2 hh = __floats2half2_rn(v0, v1);
    h = *reinterpret_cast<uint32_t*>(&hh);
    float r0 = v0 - __low2float(hh);
    float r1 = v1 - __high2float(hh);
    __half2 ll = __floats2half2_rn(r0, r1);
    l = *reinterpret_cast<uint32_t*>(&ll);
}
__device__ __forceinline__ uint32_t pack1(float v0, float v1) {
    __half2 hh = __floats2half2_rn(v0, v1);
    return *reinterpret_cast<uint32_t*>(&hh);
}

// ================ weight pre-split: ALL 6 convs in one launch ================
// Per chunk (16 cin): [tap][co 0..63][tig 0..3] uint2 = {b(pair tig), b(pair tig+4)}
__global__ void split_all(const float* __restrict__ w1, const float* __restrict__ w2,
                          const float* __restrict__ w3, const float* __restrict__ w4,
                          const float* __restrict__ w5, const float* __restrict__ w6,
                          uint2* __restrict__ dst)
{
    int idx = blockIdx.x * blockDim.x + threadIdx.x;
    if (idx >= 25 * 2304) return;
    int cg = idx / 2304;
    int r  = idx % 2304;
    const float* w; int CIN, COUT, ch;
    if      (cg < 2)  { w = w1; CIN = 24;  COUT = 64; ch = cg; }
    else if (cg < 6)  { w = w2; CIN = 64;  COUT = 64; ch = cg - 2; }
    else if (cg < 10) { w = w3; CIN = 64;  COUT = 4;  ch = cg - 6; }
    else if (cg < 17) { w = w4; CIN = 100; COUT = 64; ch = cg - 10; }
    else if (cg < 21) { w = w5; CIN = 64;  COUT = 64; ch = cg - 17; }
    else              { w = w6; CIN = 64;  COUT = 64; ch = cg - 21; }
    int tap = r / 256;
    int co  = (r % 256) >> 2;
    int tig = r & 3;
    auto f = [&](int k) -> float {
        return (co < COUT && k < CIN) ? w[((size_t)co * CIN + k) * 9 + tap] : 0.f;
    };
    int k0 = ch * 16 + tig * 2;
    int k1 = ch * 16 + (tig + 4) * 2;
    dst[idx] = make_uint2(pack1(f(k0), f(k0 + 1)), pack1(f(k1), f(k1 + 1)));
}

// ================ fp16 2-term mma.sync implicit-GEMM 3x3 conv ================
// Block 256 thr (8 warps) = 2 rows x 128 px; warp w -> row (w>>2),
// px [(w&3)*32, +32). Chunk = 16 cin (8 pairs); A double-buffered (16B
// cp.async over 4 input rows, halo amortized), W single-buffered (16B linear).
// A smem: [buf][hi/lo][pair][trow 0..3][140], pair stride 568 (==24 mod 32:
//   LDS banks {0,24,16,8}+g conflict-free). Word xl' <-> gx = x0 + xl' - 4.
// W smem: [tap][co][tig] uint2 (restaged per chunk via uint4 linear copy).
// Per tap: 16 hi-MMAs then 16 lo-MMAs per warp (breaks accumulator RAW).
template <int PA, int PR, int COUT, int NT8, int ACT, int TO_F32, int FUSE>
__global__ void __launch_bounds__(256, 2)
conv_f16(const uint32_t* __restrict__ inp, const uint2* __restrict__ wsc,
         const float* __restrict__ bias, float* __restrict__ outf,
         uint32_t* __restrict__ outs,
         const float* __restrict__ ft0, const float* __restrict__ ft1,
         const float* __restrict__ dd, const float* __restrict__ ca,
         const float* __restrict__ cb, float* __restrict__ out_fusion,
         float* __restrict__ out_sigma, uint32_t* __restrict__ din)
{
    constexpr int NC   = PA / 8;
    constexpr int PSTR = 568;              // pair stride (4 rows x 140, padded)
    constexpr int AWH  = 8 * PSTR;         // 4544 words per hi/lo half
    constexpr int AW   = 2 * AWH;          // 9088 words per A buffer
    constexpr int PO   = (COUT >= 8) ? COUT / 2 : 2;

    extern __shared__ uint32_t sm[];
    uint32_t* smA = sm;                    // [2][AW]
    uint32_t* smW = sm + 2 * AW;           // [4608]
    const uint32_t a_u = smem_u32(smA);
    const uint32_t w_u = smem_u32(smW);

    const int tid  = threadIdx.x;
    const int wid  = tid >> 5;
    const int lane = tid & 31;
    const int tig  = lane & 3;
    const int g    = lane >> 2;
    const int wr   = wid >> 2;             // warp's row within block (0/1)
    const int wx   = (wid & 3) * 32;       // warp's px base within 128
    const int y0   = (blockIdx.x >> 1) * 2;
    const int x0   = (blockIdx.x & 1) * 128;
    const int b    = blockIdx.y;

    const size_t loIn = (size_t)B * PA * HW;

    float acc[2][NT8][4];
#pragma unroll
    for (int mi = 0; mi < 2; mi++)
#pragma unroll
        for (int nt = 0; nt < NT8; nt++)
#pragma unroll
            for (int e = 0; e < 4; e++) acc[mi][nt][e] = 0.f;

    // ---- A stager: 16B vectors; 8 pairs x 4 rows x 35 groups per chunk ----
    auto issue_A = [&](int ch, int buf) {
#pragma unroll 1
        for (int i = tid; i < 1120; i += 256) {
            int j    = i % 35;
            int row  = i / 35;             // pr*4 + tr
            int tr   = row & 3;
            int pr   = row >> 2;
            int pair = ch * 8 + pr;
            int gy   = y0 + tr - 1;
            int gx0  = x0 - 4 + 4 * j;
            bool v = (gy >= 0) & (gy < H) & (gx0 >= 0) & (gx0 < W) &
                     (PA == PR || pair < PR);
            size_t so = v ? ((size_t)(b * PA + pair) * HW + (size_t)gy * W + gx0) : 0;
            uint32_t dA = a_u + (uint32_t)(buf * AW + pr * PSTR + tr * 140 + 4 * j) * 4u;
            CP_ASYNC16Z(dA,            inp + so,        v ? 16 : 0);
            CP_ASYNC16Z(dA + AWH * 4u, inp + loIn + so, v ? 16 : 0);
        }
    };
    // ---- W stager: pure linear copy, 16B vectors (1152 uint4) ----
    auto issue_W = [&](int ch) {
        const uint4* ws = (const uint4*)(wsc + ch * 2304);
#pragma unroll 1
        for (int i = tid; i < 1152; i += 256)
            CP_ASYNC16(w_u + (uint32_t)i * 16u, ws + i);
    };

    issue_A(0, 0);
    CP_COMMIT();

    for (int ch = 0; ch < NC; ch++) {
        issue_W(ch);
        CP_COMMIT();
        if (ch + 1 < NC) {
            issue_A(ch + 1, (ch + 1) & 1);
            CP_COMMIT();
            CP_WAIT1();                    // A(ch) + W(ch) complete
        } else {
            CP_WAIT0();
        }
        __syncthreads();

        const uint32_t* Ah = smA + (ch & 1) * AW;
        const uint32_t* Al = Ah + AWH;
        const uint2*    Wb = (const uint2*)smW;
        const int xbase = wx + g + 3;      // +3: dst shift of A rows

#pragma unroll
        for (int tap = 0; tap < 9; tap++) {
            const int dy = tap / 3, dx = tap % 3;
            const int trow = wr + dy;      // tile row 0..3
            uint32_t aH[2][4], aL[2][4];
#pragma unroll
            for (int mi = 0; mi < 2; mi++) {
                const int base = trow * 140 + xbase + mi * 16 + dx;
                aH[mi][0] = Ah[tig * PSTR + base];
                aH[mi][1] = Ah[tig * PSTR + base + 8];
                aH[mi][2] = Ah[(tig + 4) * PSTR + base];
                aH[mi][3] = Ah[(tig + 4) * PSTR + base + 8];
                aL[mi][0] = Al[tig * PSTR + base];
                aL[mi][1] = Al[tig * PSTR + base + 8];
                aL[mi][2] = Al[(tig + 4) * PSTR + base];
                aL[mi][3] = Al[(tig + 4) * PSTR + base + 8];
            }
            uint2 wreg[NT8];
#pragma unroll
            for (int nt = 0; nt < NT8; nt++)
                wreg[nt] = Wb[tap * 256 + (nt * 8 + g) * 4 + tig];
#pragma unroll
            for (int nt = 0; nt < NT8; nt++) {       // hi pass
                mma_f16(acc[0][nt], aH[0], wreg[nt].x, wreg[nt].y);
                mma_f16(acc[1][nt], aH[1], wreg[nt].x, wreg[nt].y);
            }
#pragma unroll
            for (int nt = 0; nt < NT8; nt++) {       // lo pass
                mma_f16(acc[0][nt], aL[0], wreg[nt].x, wreg[nt].y);
                mma_f16(acc[1][nt], aL[1], wreg[nt].x, wreg[nt].y);
            }
        }
        __syncthreads();
    }

    // ---- epilogue ----
    const int yout = y0 + wr;
    float* gsm = (float*)smA;              // reused (all reads done)
#pragma unroll
    for (int nt = 0; nt < NT8; nt++) {
        const int co0 = nt * 8 + tig * 2;
        if (COUT < 8 && co0 >= COUT) continue;
        const float bs0 = __ldg(&bias[co0]);
        const float bs1 = __ldg(&bias[co0 + 1]);
#pragma unroll
        for (int mi = 0; mi < 2; mi++) {
            const int px = wx + mi * 16 + g;
            float v0 = acc[mi][nt][0] + bs0;
            float v1 = acc[mi][nt][1] + bs1;
            float v2 = acc[mi][nt][2] + bs0;
            float v3 = acc[mi][nt][3] + bs1;
            if (ACT == 0) {
                v0 = fmaxf(v0, 0.f); v1 = fmaxf(v1, 0.f);
                v2 = fmaxf(v2, 0.f); v3 = fmaxf(v3, 0.f);
            } else if (ACT == 1) {
                v0 = 1.f / (1.f + __expf(-v0)); v1 = 1.f / (1.f + __expf(-v1));
                v2 = 1.f / (1.f + __expf(-v2)); v3 = 1.f / (1.f + __expf(-v3));
            }
            if (TO_F32) {
                float* o0 = outf + ((size_t)b * COUT + co0) * HW
                            + (size_t)yout * W + x0;
                float* o1 = o0 + HW;
                o0[px]     = v0;  o1[px]     = v1;
                o0[px + 8] = v2;  o1[px + 8] = v3;
            } else {
                const int pair = nt * 4 + tig;
                uint32_t h0, l0, h1, l1;
                packA(v0, v1, h0, l0);
                packA(v2, v3, h1, l1);
                size_t o = (size_t)(b * PO + pair) * HW + (size_t)yout * W + x0 + px;
                size_t loO = (size_t)B * PO * HW;
                outs[o]           = h0;
                outs[o + 8]       = h1;
                outs[loO + o]     = l0;
                outs[loO + o + 8] = l1;
            }
            if (FUSE) {                    // gamma -> smem [c][row][px]
                gsm[(co0)     * 264 + wr * 132 + px]     = v0;
                gsm[(co0 + 1) * 264 + wr * 132 + px]     = v1;
                gsm[(co0)     * 264 + wr * 132 + px + 8] = v2;
                gsm[(co0 + 1) * 264 + wr * 132 + px + 8] = v3;
            }
        }
    }

    // ---- fused elementwise stage (conv3 only): fusion_out / sigma / din ----
    if (FUSE) {
        __syncthreads();
        const int row = tid >> 7;          // 0/1
        const int px  = tid & 127;
        const int q   = (y0 + row) * W + x0 + px;
        const float* f0 = ft0 + (size_t)b * 64 * HW + q;
        const float* f1 = ft1 + (size_t)b * 64 * HW + q;
        const float* dv = dd  + (size_t)b * 16 * HW + q;
        float* ofu = out_fusion + (size_t)b * 64 * HW + q;
        float* osg = out_sigma  + (size_t)b * 4 * HW + q;
        const float a = *ca, bo = *cb;
        const size_t loD = (size_t)B * 56 * HW;

        float g4[4];
#pragma unroll
        for (int c = 0; c < 4; c++) g4[c] = gsm[c * 264 + row * 132 + px];

        auto st = [&](int pair, float v0, float v1) {
            uint32_t h, l;
            packA(v0, v1, h, l);
            size_t o = (size_t)(b * 56 + pair) * HW + q;
            din[o] = h;
            din[loD + o] = l;
        };
#pragma unroll
        for (int c = 0; c < 32; c++) {
            float t00 = f0[(size_t)(2 * c) * HW],     t10 = f1[(size_t)(2 * c) * HW];
            float t01 = f0[(size_t)(2 * c + 1) * HW], t11 = f1[(size_t)(2 * c + 1) * HW];
            float gm = g4[c >> 3];
            float r0 = t00 + gm * (t10 - t00);
            float r1 = t01 + gm * (t11 - t01);
            ofu[(size_t)(2 * c) * HW]     = r0;
            ofu[(size_t)(2 * c + 1) * HW] = r1;
            st(c, r0, r1);
        }
#pragma unroll
        for (int j = 0; j < 8; j++)
            st(32 + j, f1[(size_t)(2 * j) * HW], f1[(size_t)(2 * j + 1) * HW]);
#pragma unroll
        for (int j = 0; j < 8; j++)
            st(40 + j, dv[(size_t)(2 * j) * HW], dv[(size_t)(2 * j + 1) * HW]);
        float sg[4];
#pragma unroll
        for (int c = 0; c < 4; c++) {
            float s0 = fminf(fmaxf(f0[(size_t)c * HW], 0.f), 1.f) * a + bo;
            float s1 = fminf(fmaxf(f1[(size_t)c * HW], 0.f), 1.f) * a + bo;
            float om = 1.f - g4[c];
            sg[c] = om * om * s0 + g4[c] * g4[c] * s1;
            osg[(size_t)c * HW] = sg[c];
        }
        st(48, sg[0], sg[1]);
        st(49, sg[2], sg[3]);
    }
}

// ---------------- prep: fusion_in -> pair-packed fp16 hi/lo ------------------
__global__ void prep_kernel(const float* __restrict__ ft0,
                            const float* __restrict__ ft1,
                            const float* __restrict__ gup,
                            const float* __restrict__ ca,
                            const float* __restrict__ cb,
                            uint32_t* __restrict__ fin)
{
    int p = blockIdx.x * blockDim.x + threadIdx.x;
    if (p >= B * HW) return;
    int b = p >> 16;
    int q = p & (HW - 1);
    const float* f0 = ft0 + (size_t)b * 64 * HW + q;
    const float* f1 = ft1 + (size_t)b * 64 * HW + q;
    const float* gu = gup + (size_t)b * 4 * HW + q;
    float a = *ca, bo = *cb;
    const size_t lo_off = (size_t)B * 16 * HW;

    auto st = [&](int pair, float v0, float v1) {
        uint32_t h, l;
        packA(v0, v1, h, l);
        size_t o = (size_t)(b * 16 + pair) * HW + q;
        fin[o] = h;
        fin[lo_off + o] = l;
    };
#pragma unroll
    for (int i = 0; i < 8; i++) {
        float d0 = fabsf(f1[(size_t)(2 * i) * HW]     - f0[(size_t)(2 * i) * HW]);
        float d1 = fabsf(f1[(size_t)(2 * i + 1) * HW] - f0[(size_t)(2 * i + 1) * HW]);
        st(i, d0, d1);
    }
    st(8, gu[0], gu[(size_t)1 * HW]);
    st(9, gu[(size_t)2 * HW], gu[(size_t)3 * HW]);
#pragma unroll
    for (int i = 0; i < 2; i++) {
        float s0 = fminf(fmaxf(f1[(size_t)(2 * i) * HW],     0.f), 1.f) * a + bo;
        float s1 = fminf(fmaxf(f1[(size_t)(2 * i + 1) * HW], 0.f), 1.f) * a + bo;
        st(10 + i, s0, s1);
    }
}

// ---------------- launch -----------------------------------------------------
template <int PA, int PR, int COUT, int NT8, int ACT, int TO_F32, int FUSE>
static inline void launch_conv(const uint32_t* in, const uint2* w,
                               const float* bi, float* of, uint32_t* os,
                               const float* ft0 = nullptr, const float* ft1 = nullptr,
                               const float* dd = nullptr, const float* ca = nullptr,
                               const float* cb = nullptr, float* ofu = nullptr,
                               float* osg = nullptr, uint32_t* din = nullptr)
{
    constexpr int SMEM = (2 * 9088 + 4608) * 4;   // 91136 B -> 2 CTAs/SM
    cudaFuncSetAttribute(conv_f16<PA, PR, COUT, NT8, ACT, TO_F32, FUSE>,
                         cudaFuncAttributeMaxDynamicSharedMemorySize, SMEM);
    conv_f16<PA, PR, COUT, NT8, ACT, TO_F32, FUSE>
        <<<dim3(H, B), 256, SMEM>>>(in, w, bi, of, os,
                                    ft0, ft1, dd, ca, cb, ofu, osg, din);
}

extern "C" void kernel_launch(void* const* d_in, const int* in_sizes, int n_in,
                              void* d_out, int out_size)
{
    const float* ft0 = (const float*)d_in[0];
    const float* ft1 = (const float*)d_in[1];
    const float* gup = (const float*)d_in[2];
    const float* dd  = (const float*)d_in[3];
    const float* ca  = (const float*)d_in[4];
    const float* cb  = (const float*)d_in[5];
    const float* fw1 = (const float*)d_in[6];
    const float* fb1 = (const float*)d_in[7];
    const float* fw2 = (const float*)d_in[8];
    const float* fb2 = (const float*)d_in[9];
    const float* fw3 = (const float*)d_in[10];
    const float* fb3 = (const float*)d_in[11];
    const float* dw1 = (const float*)d_in[12];
    const float* db1 = (const float*)d_in[13];
    const float* dw2 = (const float*)d_in[14];
    const float* db2 = (const float*)d_in[15];
    const float* dw3 = (const float*)d_in[16];
    const float* db3 = (const float*)d_in[17];

    float* out        = (float*)d_out;
    float* out_fusion = out;
    float* out_den    = out + (size_t)B * 64 * HW;
    float* out_gamma  = out + (size_t)2 * B * 64 * HW;
    float* out_sigma  = out_gamma + (size_t)B * 4 * HW;

    float *fin_f, *bufA_f, *bufB_f, *din_f, *wsc_f;
    cudaGetSymbolAddress((void**)&fin_f,  g_fin);
    cudaGetSymbolAddress((void**)&bufA_f, g_bufA);
    cudaGetSymbolAddress((void**)&bufB_f, g_bufB);
    cudaGetSymbolAddress((void**)&din_f,  g_din);
    cudaGetSymbolAddress((void**)&wsc_f,  g_wsc);
    uint32_t* fin  = (uint32_t*)fin_f;
    uint32_t* bufA = (uint32_t*)bufA_f;
    uint32_t* bufB = (uint32_t*)bufB_f;
    uint32_t* din  = (uint32_t*)din_f;
    uint2*    wsc  = (uint2*)wsc_f;

    // chunk offsets (x2304 uint2): w1@0(2) w2@2(4) w3@6(4) w4@10(7) w5@17(4) w6@21(4)
    split_all<<<(25 * 2304 + 255) / 256, 256>>>(fw1, fw2, fw3, dw1, dw2, dw3, wsc);

    prep_kernel<<<(B * HW + 255) / 256, 256>>>(ft0, ft1, gup, ca, cb, fin);

    launch_conv<16, 12, 64, 8, 0, 0, 0>(fin,  wsc,              fb1, nullptr, bufA);
    launch_conv<32, 32, 64, 8, 0, 0, 0>(bufA, wsc + 2  * 2304,  fb2, nullptr, bufB);
    launch_conv<32, 32,  4, 1, 1, 1, 1>(bufB, wsc + 6  * 2304,  fb3, out_gamma, nullptr,
                                        ft0, ft1, dd, ca, cb,
                                        out_fusion, out_sigma, din);
    launch_conv<56, 50, 64, 8, 0, 0, 0>(din,  wsc + 10 * 2304,  db1, nullptr, bufA);
    launch_conv<32, 32, 64, 8, 0, 0, 0>(bufA, wsc + 17 * 2304,  db2, nullptr, bufB);
    launch_conv<32, 32, 64, 8, 2, 1, 0>(bufB, wsc + 21 * 2304,  db3, out_den, nullptr);
}

// round 17
// speedup vs baseline: 1.2664x; 1.1132x over previous
#include <cuda_runtime.h>
#include <cuda_fp16.h>
#include <cstdint>
#include <math.h>

#define H 256
#define W 256
#define B 4
#define HW 65536

// ---------------- scratch (static device globals; no runtime allocation) ----
// Activation scratch: fp16x2 pair-packed, [hi | lo] plane halves.
__device__ float g_fin [2 * B * 16 * HW];   // fusion_in,  16 pair-planes (12 real)
__device__ float g_bufA[2 * B * 32 * HW];   // conv1/conv4 out (32 pairs)
__device__ float g_bufB[2 * B * 32 * HW];   // conv2/conv5 out
__device__ float g_din [2 * B * 56 * HW];   // denoise_in, 56 pair-planes (50 real)
__device__ float g_wsc [57600 * 2];         // pre-split weights (uint2 units)

// ---------------- PTX helpers ------------------------------------------------
__device__ __forceinline__ uint32_t smem_u32(const void* p) {
    uint32_t a;
    asm("{ .reg .u64 t; cvta.to.shared.u64 t, %1; cvt.u32.u64 %0, t; }"
        : "=r"(a) : "l"(p));
    return a;
}
#define CP_ASYNC16(dst, src) \
    asm volatile("cp.async.ca.shared.global [%0], [%1], 16;" \
        :: "r"(dst), "l"(src))
#define CP_ASYNC16Z(dst, src, sz) \
    asm volatile("cp.async.cg.shared.global [%0], [%1], 16, %2;" \
        :: "r"(dst), "l"(src), "r"(sz))
#define CP_COMMIT() asm volatile("cp.async.commit_group;" ::: "memory")
#define CP_WAIT0()  asm volatile("cp.async.wait_group 0;" ::: "memory")
#define CP_WAIT1()  asm volatile("cp.async.wait_group 1;" ::: "memory")

__device__ __forceinline__ void mma_f16(float* c, const uint32_t* a,
                                        uint32_t b0, uint32_t b1) {
    asm volatile(
        "mma.sync.aligned.m16n8k16.row.col.f32.f16.f16.f32 "
        "{%0,%1,%2,%3}, {%4,%5,%6,%7}, {%8,%9}, {%0,%1,%2,%3};"
        : "+f"(c[0]), "+f"(c[1]), "+f"(c[2]), "+f"(c[3])
        : "r"(a[0]), "r"(a[1]), "r"(a[2]), "r"(a[3]), "r"(b0), "r"(b1));
}
// activation pack: hi = f16x2(v0,v1), lo = f16x2 of residuals
__device__ __forceinline__ void packA(float v0, float v1,
                                      uint32_t& h, uint32_t& l) {
    __half2 hh = __floats2half2_rn(v0, v1);
    h = *reinterpret_cast<uint32_t*>(&hh);
    float r0 = v0 - __low2float(hh);
    float r1 = v1 - __high2float(hh);
    __half2 ll = __floats2half2_rn(r0, r1);
    l = *reinterpret_cast<uint32_t*>(&ll);
}
__device__ __forceinline__ uint32_t pack1(float v0, float v1) {
    __half2 hh = __floats2half2_rn(v0, v1);
    return *reinterpret_cast<uint32_t*>(&hh);
}

// ================ weight pre-split: ALL 6 convs in one launch ================
// Per chunk (16 cin): [tap][co 0..63][tig 0..3] uint2 = {b(pair tig), b(pair tig+4)}
__global__ void split_all(const float* __restrict__ w1, const float* __restrict__ w2,
                          const float* __restrict__ w3, const float* __restrict__ w4,
                          const float* __restrict__ w5, const float* __restrict__ w6,
                          uint2* __restrict__ dst)
{
    int idx = blockIdx.x * blockDim.x + threadIdx.x;
    if (idx >= 25 * 2304) return;
    int cg = idx / 2304;
    int r  = idx % 2304;
    const float* w; int CIN, COUT, ch;
    if      (cg < 2)  { w = w1; CIN = 24;  COUT = 64; ch = cg; }
    else if (cg < 6)  { w = w2; CIN = 64;  COUT = 64; ch = cg - 2; }
    else if (cg < 10) { w = w3; CIN = 64;  COUT = 4;  ch = cg - 6; }
    else if (cg < 17) { w = w4; CIN = 100; COUT = 64; ch = cg - 10; }
    else if (cg < 21) { w = w5; CIN = 64;  COUT = 64; ch = cg - 17; }
    else              { w = w6; CIN = 64;  COUT = 64; ch = cg - 21; }
    int tap = r / 256;
    int co  = (r % 256) >> 2;
    int tig = r & 3;
    auto f = [&](int k) -> float {
        return (co < COUT && k < CIN) ? w[((size_t)co * CIN + k) * 9 + tap] : 0.f;
    };
    int k0 = ch * 16 + tig * 2;
    int k1 = ch * 16 + (tig + 4) * 2;
    dst[idx] = make_uint2(pack1(f(k0), f(k0 + 1)), pack1(f(k1), f(k1 + 1)));
}

// ================ fp16 mma.sync implicit-GEMM 3x3 conv =======================
// Block 256 thr (8 warps) = 2 rows x 128 px; warp w -> row (w>>2),
// px [(w&3)*32, +32). Chunk = 16 cin (8 pairs); A double-buffered (16B
// cp.async over 4 input rows, halo amortized), W single-buffered (16B linear).
// A smem: [buf][hi/lo][pair][trow 0..3][140], pair stride 568 (==24 mod 32:
//   LDS banks {0,24,16,8}+g conflict-free). Word xl' <-> gx = x0 + xl' - 4.
// W smem: [tap][co][tig] uint2 (restaged per chunk via uint4 linear copy).
// TERMS=2: A = hi+lo fp16 (22-bit effective), 32 MMAs/tap/warp.
// TERMS=1: A = hi only (11-bit, R5-validated for fusion path), 16 MMAs/tap.
template <int PA, int PR, int COUT, int NT8, int ACT, int TO_F32, int FUSE, int TERMS>
__global__ void __launch_bounds__(256, 2)
conv_f16(const uint32_t* __restrict__ inp, const uint2* __restrict__ wsc,
         const float* __restrict__ bias, float* __restrict__ outf,
         uint32_t* __restrict__ outs,
         const float* __restrict__ ft0, const float* __restrict__ ft1,
         const float* __restrict__ dd, const float* __restrict__ ca,
         const float* __restrict__ cb, float* __restrict__ out_fusion,
         float* __restrict__ out_sigma, uint32_t* __restrict__ din)
{
    constexpr int NC   = PA / 8;
    constexpr int PSTR = 568;              // pair stride (4 rows x 140, padded)
    constexpr int AWH  = 8 * PSTR;         // 4544 words per hi/lo half
    constexpr int AW   = 2 * AWH;          // 9088 words per A buffer
    constexpr int PO   = (COUT >= 8) ? COUT / 2 : 2;

    extern __shared__ uint32_t sm[];
    uint32_t* smA = sm;                    // [2][AW]
    uint32_t* smW = sm + 2 * AW;           // [4608]
    const uint32_t a_u = smem_u32(smA);
    const uint32_t w_u = smem_u32(smW);

    const int tid  = threadIdx.x;
    const int wid  = tid >> 5;
    const int lane = tid & 31;
    const int tig  = lane & 3;
    const int g    = lane >> 2;
    const int wr   = wid >> 2;             // warp's row within block (0/1)
    const int wx   = (wid & 3) * 32;       // warp's px base within 128
    const int y0   = (blockIdx.x >> 1) * 2;
    const int x0   = (blockIdx.x & 1) * 128;
    const int b    = blockIdx.y;

    const size_t loIn = (size_t)B * PA * HW;

    float acc[2][NT8][4];
#pragma unroll
    for (int mi = 0; mi < 2; mi++)
#pragma unroll
        for (int nt = 0; nt < NT8; nt++)
#pragma unroll
            for (int e = 0; e < 4; e++) acc[mi][nt][e] = 0.f;

    // ---- A stager: 16B vectors; 8 pairs x 4 rows x 35 groups per chunk ----
    auto issue_A = [&](int ch, int buf) {
#pragma unroll 1
        for (int i = tid; i < 1120; i += 256) {
            int j    = i % 35;
            int row  = i / 35;             // pr*4 + tr
            int tr   = row & 3;
            int pr   = row >> 2;
            int pair = ch * 8 + pr;
            int gy   = y0 + tr - 1;
            int gx0  = x0 - 4 + 4 * j;
            bool v = (gy >= 0) & (gy < H) & (gx0 >= 0) & (gx0 < W) &
                     (PA == PR || pair < PR);
            size_t so = v ? ((size_t)(b * PA + pair) * HW + (size_t)gy * W + gx0) : 0;
            uint32_t dA = a_u + (uint32_t)(buf * AW + pr * PSTR + tr * 140 + 4 * j) * 4u;
            CP_ASYNC16Z(dA, inp + so, v ? 16 : 0);
            if (TERMS == 2)
                CP_ASYNC16Z(dA + AWH * 4u, inp + loIn + so, v ? 16 : 0);
        }
    };
    // ---- W stager: pure linear copy, 16B vectors (1152 uint4) ----
    auto issue_W = [&](int ch) {
        const uint4* ws = (const uint4*)(wsc + ch * 2304);
#pragma unroll 1
        for (int i = tid; i < 1152; i += 256)
            CP_ASYNC16(w_u + (uint32_t)i * 16u, ws + i);
    };

    issue_A(0, 0);
    CP_COMMIT();

    for (int ch = 0; ch < NC; ch++) {
        issue_W(ch);
        CP_COMMIT();
        if (ch + 1 < NC) {
            issue_A(ch + 1, (ch + 1) & 1);
            CP_COMMIT();
            CP_WAIT1();                    // A(ch) + W(ch) complete
        } else {
            CP_WAIT0();
        }
        __syncthreads();

        const uint32_t* Ah = smA + (ch & 1) * AW;
        const uint32_t* Al = Ah + AWH;
        const uint2*    Wb = (const uint2*)smW;
        const int xbase = wx + g + 3;      // +3: dst shift of A rows

#pragma unroll
        for (int tap = 0; tap < 9; tap++) {
            const int dy = tap / 3, dx = tap % 3;
            const int trow = wr + dy;      // tile row 0..3
            uint32_t aH[2][4], aL[2][4];
#pragma unroll
            for (int mi = 0; mi < 2; mi++) {
                const int base = trow * 140 + xbase + mi * 16 + dx;
                aH[mi][0] = Ah[tig * PSTR + base];
                aH[mi][1] = Ah[tig * PSTR + base + 8];
                aH[mi][2] = Ah[(tig + 4) * PSTR + base];
                aH[mi][3] = Ah[(tig + 4) * PSTR + base + 8];
                if (TERMS == 2) {
                    aL[mi][0] = Al[tig * PSTR + base];
                    aL[mi][1] = Al[tig * PSTR + base + 8];
                    aL[mi][2] = Al[(tig + 4) * PSTR + base];
                    aL[mi][3] = Al[(tig + 4) * PSTR + base + 8];
                }
            }
            uint2 wreg[NT8];
#pragma unroll
            for (int nt = 0; nt < NT8; nt++)
                wreg[nt] = Wb[tap * 256 + (nt * 8 + g) * 4 + tig];
#pragma unroll
            for (int nt = 0; nt < NT8; nt++) {       // hi pass
                mma_f16(acc[0][nt], aH[0], wreg[nt].x, wreg[nt].y);
                mma_f16(acc[1][nt], aH[1], wreg[nt].x, wreg[nt].y);
            }
            if (TERMS == 2) {
#pragma unroll
                for (int nt = 0; nt < NT8; nt++) {   // lo pass
                    mma_f16(acc[0][nt], aL[0], wreg[nt].x, wreg[nt].y);
                    mma_f16(acc[1][nt], aL[1], wreg[nt].x, wreg[nt].y);
                }
            }
        }
        __syncthreads();
    }

    // ---- epilogue ----
    const int yout = y0 + wr;
    float* gsm = (float*)smA;              // reused (all reads done)
#pragma unroll
    for (int nt = 0; nt < NT8; nt++) {
        const int co0 = nt * 8 + tig * 2;
        if (COUT < 8 && co0 >= COUT) continue;
        const float bs0 = __ldg(&bias[co0]);
        const float bs1 = __ldg(&bias[co0 + 1]);
#pragma unroll
        for (int mi = 0; mi < 2; mi++) {
            const int px = wx + mi * 16 + g;
            float v0 = acc[mi][nt][0] + bs0;
            float v1 = acc[mi][nt][1] + bs1;
            float v2 = acc[mi][nt][2] + bs0;
            float v3 = acc[mi][nt][3] + bs1;
            if (ACT == 0) {
                v0 = fmaxf(v0, 0.f); v1 = fmaxf(v1, 0.f);
                v2 = fmaxf(v2, 0.f); v3 = fmaxf(v3, 0.f);
            } else if (ACT == 1) {
                v0 = 1.f / (1.f + __expf(-v0)); v1 = 1.f / (1.f + __expf(-v1));
                v2 = 1.f / (1.f + __expf(-v2)); v3 = 1.f / (1.f + __expf(-v3));
            }
            if (TO_F32) {
                float* o0 = outf + ((size_t)b * COUT + co0) * HW
                            + (size_t)yout * W + x0;
                float* o1 = o0 + HW;
                o0[px]     = v0;  o1[px]     = v1;
                o0[px + 8] = v2;  o1[px + 8] = v3;
            } else {
                const int pair = nt * 4 + tig;
                uint32_t h0, l0, h1, l1;
                packA(v0, v1, h0, l0);
                packA(v2, v3, h1, l1);
                size_t o = (size_t)(b * PO + pair) * HW + (size_t)yout * W + x0 + px;
                size_t loO = (size_t)B * PO * HW;
                outs[o]           = h0;
                outs[o + 8]       = h1;
                outs[loO + o]     = l0;
                outs[loO + o + 8] = l1;
            }
            if (FUSE) {                    // gamma -> smem [c][row][px]
                gsm[(co0)     * 264 + wr * 132 + px]     = v0;
                gsm[(co0 + 1) * 264 + wr * 132 + px]     = v1;
                gsm[(co0)     * 264 + wr * 132 + px + 8] = v2;
                gsm[(co0 + 1) * 264 + wr * 132 + px + 8] = v3;
            }
        }
    }

    // ---- fused elementwise stage (conv3 only): fusion_out / sigma / din ----
    if (FUSE) {
        __syncthreads();
        const int row = tid >> 7;          // 0/1
        const int px  = tid & 127;
        const int q   = (y0 + row) * W + x0 + px;
        const float* f0 = ft0 + (size_t)b * 64 * HW + q;
        const float* f1 = ft1 + (size_t)b * 64 * HW + q;
        const float* dv = dd  + (size_t)b * 16 * HW + q;
        float* ofu = out_fusion + (size_t)b * 64 * HW + q;
        float* osg = out_sigma  + (size_t)b * 4 * HW + q;
        const float a = *ca, bo = *cb;
        const size_t loD = (size_t)B * 56 * HW;

        float g4[4];
#pragma unroll
        for (int c = 0; c < 4; c++) g4[c] = gsm[c * 264 + row * 132 + px];

        auto st = [&](int pair, float v0, float v1) {
            uint32_t h, l;
            packA(v0, v1, h, l);
            size_t o = (size_t)(b * 56 + pair) * HW + q;
            din[o] = h;
            din[loD + o] = l;
        };
#pragma unroll
        for (int c = 0; c < 32; c++) {
            float t00 = f0[(size_t)(2 * c) * HW],     t10 = f1[(size_t)(2 * c) * HW];
            float t01 = f0[(size_t)(2 * c + 1) * HW], t11 = f1[(size_t)(2 * c + 1) * HW];
            float gm = g4[c >> 3];
            float r0 = t00 + gm * (t10 - t00);
            float r1 = t01 + gm * (t11 - t01);
            ofu[(size_t)(2 * c) * HW]     = r0;
            ofu[(size_t)(2 * c + 1) * HW] = r1;
            st(c, r0, r1);
        }
#pragma unroll
        for (int j = 0; j < 8; j++)
            st(32 + j, f1[(size_t)(2 * j) * HW], f1[(size_t)(2 * j + 1) * HW]);
#pragma unroll
        for (int j = 0; j < 8; j++)
            st(40 + j, dv[(size_t)(2 * j) * HW], dv[(size_t)(2 * j + 1) * HW]);
        float sg[4];
#pragma unroll
        for (int c = 0; c < 4; c++) {
            float s0 = fminf(fmaxf(f0[(size_t)c * HW], 0.f), 1.f) * a + bo;
            float s1 = fminf(fmaxf(f1[(size_t)c * HW], 0.f), 1.f) * a + bo;
            float om = 1.f - g4[c];
            sg[c] = om * om * s0 + g4[c] * g4[c] * s1;
            osg[(size_t)c * HW] = sg[c];
        }
        st(48, sg[0], sg[1]);
        st(49, sg[2], sg[3]);
    }
}

// ---------------- prep: fusion_in -> pair-packed fp16 hi/lo ------------------
__global__ void prep_kernel(const float* __restrict__ ft0,
                            const float* __restrict__ ft1,
                            const float* __restrict__ gup,
                            const float* __restrict__ ca,
                            const float* __restrict__ cb,
                            uint32_t* __restrict__ fin)
{
    int p = blockIdx.x * blockDim.x + threadIdx.x;
    if (p >= B * HW) return;
    int b = p >> 16;
    int q = p & (HW - 1);
    const float* f0 = ft0 + (size_t)b * 64 * HW + q;
    const float* f1 = ft1 + (size_t)b * 64 * HW + q;
    const float* gu = gup + (size_t)b * 4 * HW + q;
    float a = *ca, bo = *cb;
    const size_t lo_off = (size_t)B * 16 * HW;

    auto st = [&](int pair, float v0, float v1) {
        uint32_t h, l;
        packA(v0, v1, h, l);
        size_t o = (size_t)(b * 16 + pair) * HW + q;
        fin[o] = h;
        fin[lo_off + o] = l;
    };
#pragma unroll
    for (int i = 0; i < 8; i++) {
        float d0 = fabsf(f1[(size_t)(2 * i) * HW]     - f0[(size_t)(2 * i) * HW]);
        float d1 = fabsf(f1[(size_t)(2 * i + 1) * HW] - f0[(size_t)(2 * i + 1) * HW]);
        st(i, d0, d1);
    }
    st(8, gu[0], gu[(size_t)1 * HW]);
    st(9, gu[(size_t)2 * HW], gu[(size_t)3 * HW]);
#pragma unroll
    for (int i = 0; i < 2; i++) {
        float s0 = fminf(fmaxf(f1[(size_t)(2 * i) * HW],     0.f), 1.f) * a + bo;
        float s1 = fminf(fmaxf(f1[(size_t)(2 * i + 1) * HW], 0.f), 1.f) * a + bo;
        st(10 + i, s0, s1);
    }
}

// ---------------- launch -----------------------------------------------------
template <int PA, int PR, int COUT, int NT8, int ACT, int TO_F32, int FUSE, int TERMS>
static inline void launch_conv(const uint32_t* in, const uint2* w,
                               const float* bi, float* of, uint32_t* os,
                               const float* ft0 = nullptr, const float* ft1 = nullptr,
                               const float* dd = nullptr, const float* ca = nullptr,
                               const float* cb = nullptr, float* ofu = nullptr,
                               float* osg = nullptr, uint32_t* din = nullptr)
{
    constexpr int SMEM = (2 * 9088 + 4608) * 4;   // 91136 B -> 2 CTAs/SM
    cudaFuncSetAttribute(conv_f16<PA, PR, COUT, NT8, ACT, TO_F32, FUSE, TERMS>,
                         cudaFuncAttributeMaxDynamicSharedMemorySize, SMEM);
    conv_f16<PA, PR, COUT, NT8, ACT, TO_F32, FUSE, TERMS>
        <<<dim3(H, B), 256, SMEM>>>(in, w, bi, of, os,
                                    ft0, ft1, dd, ca, cb, ofu, osg, din);
}

extern "C" void kernel_launch(void* const* d_in, const int* in_sizes, int n_in,
                              void* d_out, int out_size)
{
    const float* ft0 = (const float*)d_in[0];
    const float* ft1 = (const float*)d_in[1];
    const float* gup = (const float*)d_in[2];
    const float* dd  = (const float*)d_in[3];
    const float* ca  = (const float*)d_in[4];
    const float* cb  = (const float*)d_in[5];
    const float* fw1 = (const float*)d_in[6];
    const float* fb1 = (const float*)d_in[7];
    const float* fw2 = (const float*)d_in[8];
    const float* fb2 = (const float*)d_in[9];
    const float* fw3 = (const float*)d_in[10];
    const float* fb3 = (const float*)d_in[11];
    const float* dw1 = (const float*)d_in[12];
    const float* db1 = (const float*)d_in[13];
    const float* dw2 = (const float*)d_in[14];
    const float* db2 = (const float*)d_in[15];
    const float* dw3 = (const float*)d_in[16];
    const float* db3 = (const float*)d_in[17];

    float* out        = (float*)d_out;
    float* out_fusion = out;
    float* out_den    = out + (size_t)B * 64 * HW;
    float* out_gamma  = out + (size_t)2 * B * 64 * HW;
    float* out_sigma  = out_gamma + (size_t)B * 4 * HW;

    float *fin_f, *bufA_f, *bufB_f, *din_f, *wsc_f;
    cudaGetSymbolAddress((void**)&fin_f,  g_fin);
    cudaGetSymbolAddress((void**)&bufA_f, g_bufA);
    cudaGetSymbolAddress((void**)&bufB_f, g_bufB);
    cudaGetSymbolAddress((void**)&din_f,  g_din);
    cudaGetSymbolAddress((void**)&wsc_f,  g_wsc);
    uint32_t* fin  = (uint32_t*)fin_f;
    uint32_t* bufA = (uint32_t*)bufA_f;
    uint32_t* bufB = (uint32_t*)bufB_f;
    uint32_t* din  = (uint32_t*)din_f;
    uint2*    wsc  = (uint2*)wsc_f;

    // chunk offsets (x2304 uint2): w1@0(2) w2@2(4) w3@6(4) w4@10(7) w5@17(4) w6@21(4)
    split_all<<<(25 * 2304 + 255) / 256, 256>>>(fw1, fw2, fw3, dw1, dw2, dw3, wsc);

    prep_kernel<<<(B * HW + 255) / 256, 256>>>(ft0, ft1, gup, ca, cb, fin);

    // fusion path: 1-term (11-bit, R5-validated). denoise path: 2-term.
    launch_conv<16, 12, 64, 8, 0, 0, 0, 1>(fin,  wsc,              fb1, nullptr, bufA);
    launch_conv<32, 32, 64, 8, 0, 0, 0, 1>(bufA, wsc + 2  * 2304,  fb2, nullptr, bufB);
    launch_conv<32, 32,  4, 1, 1, 1, 1, 1>(bufB, wsc + 6  * 2304,  fb3, out_gamma, nullptr,
                                           ft0, ft1, dd, ca, cb,
                                           out_fusion, out_sigma, din);
    launch_conv<56, 50, 64, 8, 0, 0, 0, 2>(din,  wsc + 10 * 2304,  db1, nullptr, bufA);
    launch_conv<32, 32, 64, 8, 0, 0, 0, 2>(bufA, wsc + 17 * 2304,  db2, nullptr, bufB);
    launch_conv<32, 32, 64, 8, 2, 1, 0, 2>(bufB, wsc + 21 * 2304,  db3, out_den, nullptr);
}